// round 11
// baseline (speedup 1.0000x reference)
#include <cuda_runtime.h>

// CollisionLoss, scalar Gram-form (minimum fma-pipe ops per pair).
// pos [B=65536, N=24, 3] f32 -> scalar f32.
// Per batch, masked pairs (i<j, i>=1, skip (2,3)):
//   sq = |p_i-p_j|^2 ; if sq < 0.25: sum += exp(-4*sq); cnt++
// out = (cnt>0 ? sum/cnt : 0) + 1e-6
// Coords pre-scaled at staging by sqrt(4*log2 e): term = 2^(-s), test s < log2 e.
// MODEL (fits R2..R10): per-SMSP issue caps at ~0.5 for scalar (FMA rt 2) and
// ~0.25-0.32 for f32x2 (FFMA2 rt ~4) -> packing never helped; only fma-pipe
// ops/pair matter. This kernel: s = (ni+nj) - 2<pi,pj> via 1 FADD + 3 FFMA,
// tail EX2 (MUFU pipe) + FSETP/FSEL (alu pipe) + FFMA + FADD
// => 6 fma-pipe ops/pair (was ~10). j-stream is 1 LDS.128 (xyz + norm).

#define THREADS 128
#define BATCH_PER_BLOCK 32
#define PTS 24
#define FLOATS_PER 72
#define ROW_V4 25                 // float4 cells per lane row (24 + 1 pad); stride
                                  // 25 f4 -> phase banks 4L mod 32 distinct per 8-lane phase
#define MAX_BLOCKS 2048

__device__ float g_psum[MAX_BLOCKS];
__device__ float g_pcnt[MAX_BLOCKS];
__device__ unsigned int g_ticket = 0;

// One pair in Gram form: 6 fma-pipe ops + 1 MUFU + 2 alu.
#define PAIRD(qx_, qy_, qz_, ni_, u_)                                \
    do {                                                             \
        float s = (ni_) + (u_).w;                                    \
        s = fmaf((qx_), (u_).x, s);                                  \
        s = fmaf((qy_), (u_).y, s);                                  \
        s = fmaf((qz_), (u_).z, s);        /* scaled |pi-pj|^2 */    \
        float e = exp2f(-s);               /* MUFU, neg folded */    \
        float w = (s < 1.44269504f) ? 1.0f : 0.0f;                   \
        lsum = fmaf(e, w, lsum);                                     \
        lcnt += w;                                                   \
    } while (0)

// i in [I0, I1] preloaded (q = -2*p, n); j streamed over (I0, 23] as float4.
// Only i<j pairs; (2,3) excluded at compile time.
template <int I0, int I1>
__device__ __forceinline__ void tri_dot(const float4* __restrict__ row,
                                        float& lsum, float& lcnt) {
    const int NI = I1 - I0 + 1;
    float qx[NI], qy[NI], qz[NI], ni[NI];
    #pragma unroll
    for (int k = 0; k < NI; k++) {
        float4 v = row[I0 + k];
        qx[k] = -2.0f * v.x;
        qy[k] = -2.0f * v.y;
        qz[k] = -2.0f * v.z;
        ni[k] = v.w;
    }
    #pragma unroll
    for (int j = I0 + 1; j <= 23; j++) {
        float4 u = row[j];                 // 1 LDS.128: x,y,z,norm
        #pragma unroll
        for (int k = 0; k < NI; k++) {
            const int i = I0 + k;
            if (i >= j) continue;             // compile-time
            if (i == 2 && j == 3) continue;   // excluded pair, compile-time
            PAIRD(qx[k], qy[k], qz[k], ni[k], u);
        }
    }
}

__global__ __launch_bounds__(THREADS, 8)
void collision_gram_kernel(const float* __restrict__ pos, float* __restrict__ out, int B) {
    __shared__ float4 smf4[BATCH_PER_BLOCK * ROW_V4];   // (x,y,z,norm) per point
    __shared__ float wsum[THREADS / 32];
    __shared__ float wcnt[THREADS / 32];
    __shared__ bool  amLast;
    float* smf = reinterpret_cast<float*>(smf4);

    const int tid   = threadIdx.x;
    const int role  = tid >> 5;
    const int lane  = tid & 31;
    const int bbase = blockIdx.x * BATCH_PER_BLOCK;
    const int valid = min(BATCH_PER_BLOCK, B - bbase);

    // ---- Stage A: coalesced float4 gmem -> smem (x,y,z per point), scaled ----
    {
        const float SCALE = 2.4022448929611436f;   // sqrt(4 * log2 e)
        const float4* src4 = reinterpret_cast<const float4*>(pos + (size_t)bbase * FLOATS_PER);
        const int n4 = valid * 18;                 // 72 floats = 18 float4 per batch
        for (int q = tid; q < n4; q += THREADS) {
            float4 v = src4[q];
            int bl = q / 18;                       // batch within block
            int w  = (q - bl * 18) << 2;           // first float index (mult of 4)
            // float index w -> point w/3, component w%3
            float vals[4] = {v.x, v.y, v.z, v.w};
            #pragma unroll
            for (int t = 0; t < 4; t++) {
                int wf = w + t;
                int p  = wf / 3;
                int c  = wf - p * 3;
                smf[(bl * ROW_V4 + p) * 4 + c] = vals[t] * SCALE;
            }
        }
    }
    __syncthreads();

    // ---- Stage B: per-point norms into .w ----
    {
        const int total = valid * PTS;
        for (int idx = tid; idx < total; idx += THREADS) {
            int bl = idx / PTS;
            int p  = idx - bl * PTS;
            float4 v = smf4[bl * ROW_V4 + p];
            float n = v.x * v.x;
            n = fmaf(v.y, v.y, n);
            n = fmaf(v.z, v.z, n);
            smf[(bl * ROW_V4 + p) * 4 + 3] = n;
        }
    }
    __syncthreads();

    float lsum = 0.0f, lcnt = 0.0f;

    if (lane < valid) {
        const float4* row = &smf4[lane * ROW_V4];
        // Roles (pairs): 0:<1,3> 62 | 1:<4,7> 70 | 2:<8,11>+<19,22> 64 | 3:<12,15>+<16,18> 56
        if (role == 0) {
            tri_dot<1, 3>(row, lsum, lcnt);
        } else if (role == 1) {
            tri_dot<4, 7>(row, lsum, lcnt);
        } else if (role == 2) {
            tri_dot<8, 11>(row, lsum, lcnt);
            tri_dot<19, 22>(row, lsum, lcnt);
        } else {
            tri_dot<12, 15>(row, lsum, lcnt);
            tri_dot<16, 18>(row, lsum, lcnt);
        }
    }

    // ---- Block reduce ----
    #pragma unroll
    for (int o = 16; o > 0; o >>= 1) {
        lsum += __shfl_down_sync(0xffffffffu, lsum, o);
        lcnt += __shfl_down_sync(0xffffffffu, lcnt, o);
    }
    if (lane == 0) { wsum[role] = lsum; wcnt[role] = lcnt; }
    __syncthreads();
    if (tid == 0) {
        float s = 0.0f, c = 0.0f;
        #pragma unroll
        for (int w = 0; w < THREADS / 32; w++) { s += wsum[w]; c += wcnt[w]; }
        g_psum[blockIdx.x] = s;
        g_pcnt[blockIdx.x] = c;
        __threadfence();
        unsigned int t = atomicAdd(&g_ticket, 1u);
        amLast = (t == gridDim.x - 1);
    }
    __syncthreads();

    // ---- Last block finalizes ----
    if (amLast) {
        const int nb = gridDim.x;
        float s = 0.0f, c = 0.0f;
        for (int i = tid; i < nb; i += THREADS) {
            s += g_psum[i];
            c += g_pcnt[i];
        }
        #pragma unroll
        for (int o = 16; o > 0; o >>= 1) {
            s += __shfl_down_sync(0xffffffffu, s, o);
            c += __shfl_down_sync(0xffffffffu, c, o);
        }
        if (lane == 0) { wsum[role] = s; wcnt[role] = c; }
        __syncthreads();
        if (tid == 0) {
            float ts = 0.0f, tc = 0.0f;
            #pragma unroll
            for (int w = 0; w < THREADS / 32; w++) { ts += wsum[w]; tc += wcnt[w]; }
            float total = (tc > 0.0f) ? (ts / fmaxf(tc, 1.0f)) : 0.0f;
            out[0] = total + 1e-6f;
            g_ticket = 0;   // reset for next graph replay
        }
    }
}

extern "C" void kernel_launch(void* const* d_in, const int* in_sizes, int n_in,
                              void* d_out, int out_size) {
    const float* pos = (const float*)d_in[0];
    const int B = in_sizes[0] / FLOATS_PER;
    int nblocks = (B + BATCH_PER_BLOCK - 1) / BATCH_PER_BLOCK;   // 2048 for B=65536
    if (nblocks > MAX_BLOCKS) nblocks = MAX_BLOCKS;
    collision_gram_kernel<<<nblocks, THREADS>>>(pos, (float*)d_out, B);
}

// round 12
// speedup vs baseline: 1.0014x; 1.0014x over previous
#include <cuda_runtime.h>

// CollisionLoss, scalar Gram-form + RAW EX2 (single-change A/B vs R11).
// pos [B=65536, N=24, 3] f32 -> scalar f32.
// Per batch, masked pairs (i<j, i>=1, skip (2,3)):
//   sq = |p_i-p_j|^2 ; if sq < 0.25: sum += exp(-4*sq); cnt++
// out = (cnt>0 ? sum/cnt : 0) + 1e-6
// Coords pre-scaled at staging by sqrt(4*log2 e): term = 2^(-s), test s < log2 e.
// R11 used exp2f() -> WITHOUT --use_fast_math that is a ~10+ instr software
// expansion (back-computed: R11 ran ~11.2M warp-instrs vs ~6M modeled).
// This round: identical kernel, but 2^(-s) via raw ex2.approx asm (1 MUFU,
// FNEG folds into the MUFU source mod). Per pair: FADD + 3 FFMA + MUFU +
// FSETP + FSEL + FFMA + FADD = 9 instrs.

#define THREADS 128
#define BATCH_PER_BLOCK 32
#define PTS 24
#define FLOATS_PER 72
#define ROW_V4 25                 // float4 cells per lane row (24 + 1 pad) -> conflict-free LDS.128
#define MAX_BLOCKS 2048

__device__ float g_psum[MAX_BLOCKS];
__device__ float g_pcnt[MAX_BLOCKS];
__device__ unsigned int g_ticket = 0;

__device__ __forceinline__ float nex2(float s) {   // 2^(-s); neg folds into MUFU src mod
    float e;
    asm("{\n\t.reg .f32 t;\n\tneg.f32 t, %1;\n\tex2.approx.f32 %0, t;\n\t}"
        : "=f"(e) : "f"(s));
    return e;
}

// One pair in Gram form: s = ni + nj - 2<pi,pj>. 9 instrs total.
#define PAIRD(qx_, qy_, qz_, ni_, u_)                                \
    do {                                                             \
        float s = (ni_) + (u_).w;                                    \
        s = fmaf((qx_), (u_).x, s);                                  \
        s = fmaf((qy_), (u_).y, s);                                  \
        s = fmaf((qz_), (u_).z, s);        /* scaled |pi-pj|^2 */    \
        float e = nex2(s);                 /* single MUFU */         \
        float w = (s < 1.44269504f) ? 1.0f : 0.0f;                   \
        lsum = fmaf(e, w, lsum);                                     \
        lcnt += w;                                                   \
    } while (0)

// i in [I0, I1] preloaded (q = -2*p, n); j streamed over (I0, 23] as float4.
// Only i<j pairs; (2,3) excluded at compile time.
template <int I0, int I1>
__device__ __forceinline__ void tri_dot(const float4* __restrict__ row,
                                        float& lsum, float& lcnt) {
    const int NI = I1 - I0 + 1;
    float qx[NI], qy[NI], qz[NI], ni[NI];
    #pragma unroll
    for (int k = 0; k < NI; k++) {
        float4 v = row[I0 + k];
        qx[k] = -2.0f * v.x;
        qy[k] = -2.0f * v.y;
        qz[k] = -2.0f * v.z;
        ni[k] = v.w;
    }
    #pragma unroll
    for (int j = I0 + 1; j <= 23; j++) {
        float4 u = row[j];                 // 1 LDS.128: x,y,z,norm
        #pragma unroll
        for (int k = 0; k < NI; k++) {
            const int i = I0 + k;
            if (i >= j) continue;             // compile-time
            if (i == 2 && j == 3) continue;   // excluded pair, compile-time
            PAIRD(qx[k], qy[k], qz[k], ni[k], u);
        }
    }
}

__global__ __launch_bounds__(THREADS, 8)
void collision_gram2_kernel(const float* __restrict__ pos, float* __restrict__ out, int B) {
    __shared__ float4 smf4[BATCH_PER_BLOCK * ROW_V4];   // (x,y,z,norm) per point
    __shared__ float wsum[THREADS / 32];
    __shared__ float wcnt[THREADS / 32];
    __shared__ bool  amLast;
    float* smf = reinterpret_cast<float*>(smf4);

    const int tid   = threadIdx.x;
    const int role  = tid >> 5;
    const int lane  = tid & 31;
    const int bbase = blockIdx.x * BATCH_PER_BLOCK;
    const int valid = min(BATCH_PER_BLOCK, B - bbase);

    // ---- Stage A: coalesced float4 gmem -> smem (x,y,z per point), scaled ----
    {
        const float SCALE = 2.4022448929611436f;   // sqrt(4 * log2 e)
        const float4* src4 = reinterpret_cast<const float4*>(pos + (size_t)bbase * FLOATS_PER);
        const int n4 = valid * 18;                 // 72 floats = 18 float4 per batch
        for (int q = tid; q < n4; q += THREADS) {
            float4 v = src4[q];
            int bl = q / 18;                       // batch within block
            int w  = (q - bl * 18) << 2;           // first float index (mult of 4)
            float vals[4] = {v.x, v.y, v.z, v.w};
            #pragma unroll
            for (int t = 0; t < 4; t++) {
                int wf = w + t;
                int p  = wf / 3;
                int c  = wf - p * 3;
                smf[(bl * ROW_V4 + p) * 4 + c] = vals[t] * SCALE;
            }
        }
    }
    __syncthreads();

    // ---- Stage B: per-point norms into .w ----
    {
        const int total = valid * PTS;
        for (int idx = tid; idx < total; idx += THREADS) {
            int bl = idx / PTS;
            int p  = idx - bl * PTS;
            float4 v = smf4[bl * ROW_V4 + p];
            float n = v.x * v.x;
            n = fmaf(v.y, v.y, n);
            n = fmaf(v.z, v.z, n);
            smf[(bl * ROW_V4 + p) * 4 + 3] = n;
        }
    }
    __syncthreads();

    float lsum = 0.0f, lcnt = 0.0f;

    if (lane < valid) {
        const float4* row = &smf4[lane * ROW_V4];
        // Roles (pairs): 0:<1,3> 62 | 1:<4,7> 70 | 2:<8,11>+<19,22> 64 | 3:<12,15>+<16,18> 56
        if (role == 0) {
            tri_dot<1, 3>(row, lsum, lcnt);
        } else if (role == 1) {
            tri_dot<4, 7>(row, lsum, lcnt);
        } else if (role == 2) {
            tri_dot<8, 11>(row, lsum, lcnt);
            tri_dot<19, 22>(row, lsum, lcnt);
        } else {
            tri_dot<12, 15>(row, lsum, lcnt);
            tri_dot<16, 18>(row, lsum, lcnt);
        }
    }

    // ---- Block reduce ----
    #pragma unroll
    for (int o = 16; o > 0; o >>= 1) {
        lsum += __shfl_down_sync(0xffffffffu, lsum, o);
        lcnt += __shfl_down_sync(0xffffffffu, lcnt, o);
    }
    if (lane == 0) { wsum[role] = lsum; wcnt[role] = lcnt; }
    __syncthreads();
    if (tid == 0) {
        float s = 0.0f, c = 0.0f;
        #pragma unroll
        for (int w = 0; w < THREADS / 32; w++) { s += wsum[w]; c += wcnt[w]; }
        g_psum[blockIdx.x] = s;
        g_pcnt[blockIdx.x] = c;
        __threadfence();
        unsigned int t = atomicAdd(&g_ticket, 1u);
        amLast = (t == gridDim.x - 1);
    }
    __syncthreads();

    // ---- Last block finalizes ----
    if (amLast) {
        const int nb = gridDim.x;
        float s = 0.0f, c = 0.0f;
        for (int i = tid; i < nb; i += THREADS) {
            s += g_psum[i];
            c += g_pcnt[i];
        }
        #pragma unroll
        for (int o = 16; o > 0; o >>= 1) {
            s += __shfl_down_sync(0xffffffffu, s, o);
            c += __shfl_down_sync(0xffffffffu, c, o);
        }
        if (lane == 0) { wsum[role] = s; wcnt[role] = c; }
        __syncthreads();
        if (tid == 0) {
            float ts = 0.0f, tc = 0.0f;
            #pragma unroll
            for (int w = 0; w < THREADS / 32; w++) { ts += wsum[w]; tc += wcnt[w]; }
            float total = (tc > 0.0f) ? (ts / fmaxf(tc, 1.0f)) : 0.0f;
            out[0] = total + 1e-6f;
            g_ticket = 0;   // reset for next graph replay
        }
    }
}

extern "C" void kernel_launch(void* const* d_in, const int* in_sizes, int n_in,
                              void* d_out, int out_size) {
    const float* pos = (const float*)d_in[0];
    const int B = in_sizes[0] / FLOATS_PER;
    int nblocks = (B + BATCH_PER_BLOCK - 1) / BATCH_PER_BLOCK;   // 2048 for B=65536
    if (nblocks > MAX_BLOCKS) nblocks = MAX_BLOCKS;
    collision_gram2_kernel<<<nblocks, THREADS>>>(pos, (float*)d_out, B);
}